// round 1
// baseline (speedup 1.0000x reference)
#include <cuda_runtime.h>
#include <math.h>
#include <stdint.h>

#define NTOK 4096
#define DIM 768
#define QKVN (3*DIM)
#define FFD 3072
#define NE 8
#define NPAIR (NTOK*2)
#define TSEQ 1024
#define NB 4
#define NH 12
#define HD 64

#define BM 128
#define BN 128
#define BKK 8

struct Scratch {
  float xln1[(size_t)NTOK*DIM];
  float qkv[(size_t)NTOK*QKVN];
  float attn[(size_t)NTOK*DIM];
  float x1[(size_t)NTOK*DIM];
  float xln2[(size_t)NTOK*DIM];
  float H[(size_t)NPAIR*FFD];
  float slot[(size_t)NPAIR*DIM];
  float pairw[NPAIR];
  int bucket[NE*NPAIR];
  int count[NE];
};
__device__ Scratch g_s;

__device__ __forceinline__ float gelu_f(float v) {
  return 0.5f * v * (1.0f + erff(v * 0.70710678118654752f));
}

// ---------------- LayerNorm: one block per row (768 = 3*256) ----------------
__global__ void ln_kernel(const float* __restrict__ in, const float* __restrict__ gam,
                          const float* __restrict__ bet, float* __restrict__ out) {
  __shared__ float red[256];
  int row = blockIdx.x;
  int tid = threadIdx.x;
  const float* x = in + (size_t)row * DIM;
  float v0 = x[tid], v1 = x[tid+256], v2 = x[tid+512];
  red[tid] = v0+v1+v2; __syncthreads();
  for (int o=128;o;o>>=1){ if (tid<o) red[tid]+=red[tid+o]; __syncthreads(); }
  float mean = red[0] * (1.0f/DIM);
  __syncthreads();
  float d0=v0-mean, d1=v1-mean, d2=v2-mean;
  red[tid] = d0*d0+d1*d1+d2*d2; __syncthreads();
  for (int o=128;o;o>>=1){ if (tid<o) red[tid]+=red[tid+o]; __syncthreads(); }
  float r = rsqrtf(red[0]*(1.0f/DIM) + 1e-5f);
  float* o = out + (size_t)row*DIM;
  o[tid]     = d0*r*gam[tid]     + bet[tid];
  o[tid+256] = d1*r*gam[tid+256] + bet[tid+256];
  o[tid+512] = d2*r*gam[tid+512] + bet[tid+512];
}

// ---------------- Generic tiled SGEMM ----------------
// MODE 0: C = A@B                       (QKV)
// MODE 1: C = A@B + resid               (proj + residual)
// MODE 2: gather A rows = token(pair), C rows = pair, gelu epilogue   (MoE up)
// MODE 3: gather A rows = pair,         C rows = pair, scale-by-w     (MoE down)
template<int MODE>
__global__ __launch_bounds__(256)
void gemm_kernel(const float* __restrict__ A, const float* __restrict__ B,
                 float* __restrict__ C, int M, int N, int K,
                 const int* __restrict__ bucket, const int* __restrict__ counts,
                 const float* __restrict__ resid, const float* __restrict__ pairw)
{
  int mcount = M;
  const int* rows = nullptr;
  if constexpr (MODE >= 2) {
    int e = blockIdx.z;
    rows = bucket + e * NPAIR;
    mcount = counts[e];
    B += (size_t)e * (size_t)K * N;
  }
  int m0 = blockIdx.y * BM;
  if (m0 >= mcount) return;
  int n0 = blockIdx.x * BN;

  __shared__ float As[BKK][BM];
  __shared__ float Bs[BKK][BN];
  int tid = threadIdx.x;
  int a_m = tid >> 1;
  int a_k = (tid & 1) * 4;
  int gm = m0 + a_m;
  int gmc = gm < mcount ? gm : (mcount - 1);
  int arow;
  if constexpr (MODE == 2) arow = rows[gmc] >> 1;
  else if constexpr (MODE == 3) arow = rows[gmc];
  else arow = gmc;
  const float* Ap = A + (size_t)arow * K + a_k;
  int b_k = tid >> 5;
  int b_n = (tid & 31) * 4;
  const float* Bp = B + (size_t)b_k * N + n0 + b_n;

  int tx = tid & 15, ty = tid >> 4;
  float acc[8][8];
  #pragma unroll
  for (int i=0;i<8;i++)
    #pragma unroll
    for (int j=0;j<8;j++) acc[i][j]=0.f;

  for (int k0 = 0; k0 < K; k0 += BKK) {
    float4 av = *(const float4*)(Ap + k0);
    As[a_k+0][a_m]=av.x; As[a_k+1][a_m]=av.y; As[a_k+2][a_m]=av.z; As[a_k+3][a_m]=av.w;
    float4 bv = *(const float4*)(Bp + (size_t)k0 * N);
    *(float4*)&Bs[b_k][b_n] = bv;
    __syncthreads();
    #pragma unroll
    for (int kk=0; kk<BKK; kk++) {
      float af[8], bf[8];
      *(float4*)&af[0] = *(const float4*)&As[kk][ty*8];
      *(float4*)&af[4] = *(const float4*)&As[kk][ty*8+4];
      *(float4*)&bf[0] = *(const float4*)&Bs[kk][tx*8];
      *(float4*)&bf[4] = *(const float4*)&Bs[kk][tx*8+4];
      #pragma unroll
      for (int i=0;i<8;i++)
        #pragma unroll
        for (int j=0;j<8;j++)
          acc[i][j] += af[i]*bf[j];
    }
    __syncthreads();
  }

  #pragma unroll
  for (int i=0;i<8;i++) {
    int gmi = m0 + ty*8 + i;
    if (gmi >= mcount) break;
    int crow; float w = 1.f;
    if constexpr (MODE >= 2) {
      int p = rows[gmi];
      crow = p;
      if constexpr (MODE == 3) w = pairw[p];
    } else crow = gmi;
    float* Cp = C + (size_t)crow * N + n0 + tx*8;
    const float* Rp = (MODE==1) ? (resid + (size_t)gmi * N + n0 + tx*8) : nullptr;
    #pragma unroll
    for (int j=0;j<8;j++) {
      float v = acc[i][j];
      if constexpr (MODE == 1) v += Rp[j];
      if constexpr (MODE == 2) v = gelu_f(v);
      if constexpr (MODE == 3) v *= w;
      Cp[j] = v;
    }
  }
}

// ---------------- Flash attention: block = (b, h, 64 q rows) ----------------
__global__ __launch_bounds__(256)
void attn_kernel(const float* __restrict__ qkv, float* __restrict__ out) {
  extern __shared__ float sm[];
  float* Qs = sm;            // [d][qi] stride 68
  float* Ks = sm + 64*68;    // [d][kj] stride 68
  float* Vs = sm + 2*64*68;  // [kj][d] stride 68
  float* Ps = sm + 3*64*68;  // [kj][qi] stride 68
  int qt = blockIdx.x, h = blockIdx.y, b = blockIdx.z;
  int tid = threadIdx.x, tx = tid & 15, ty = tid >> 4;
  const float* base = qkv + (size_t)b * TSEQ * QKVN;
  int qcol = h*HD, kcol = DIM + h*HD, vcol = 2*DIM + h*HD;

  for (int idx = tid; idx < 64*64; idx += 256) {
    int r = idx >> 6, d = idx & 63;
    Qs[d*68 + r] = base[(size_t)(qt*64 + r)*QKVN + qcol + d] * 0.125f;
  }
  float m_r[4], l_r[4], O[4][4];
  #pragma unroll
  for (int i=0;i<4;i++){ m_r[i]=-1e30f; l_r[i]=0.f;
    #pragma unroll
    for (int j=0;j<4;j++) O[i][j]=0.f; }

  for (int kt=0; kt<16; kt++) {
    __syncthreads();   // prior P@V done (and Q load visible on kt=0)
    for (int idx = tid; idx < 64*64; idx += 256) {
      int r = idx >> 6, d = idx & 63;
      const float* rp = base + (size_t)(kt*64 + r)*QKVN;
      Ks[d*68 + r] = rp[kcol + d];
      Vs[r*68 + d] = rp[vcol + d];
    }
    __syncthreads();

    float Sf[4][4];
    #pragma unroll
    for (int i=0;i<4;i++)
      #pragma unroll
      for (int j=0;j<4;j++) Sf[i][j]=0.f;
    #pragma unroll 4
    for (int d=0; d<64; d++) {
      float4 a4 = *(const float4*)(Qs + d*68 + ty*4);
      float4 b4 = *(const float4*)(Ks + d*68 + tx*4);
      float aa[4]={a4.x,a4.y,a4.z,a4.w};
      float bb[4]={b4.x,b4.y,b4.z,b4.w};
      #pragma unroll
      for (int i=0;i<4;i++)
        #pragma unroll
        for (int j=0;j<4;j++) Sf[i][j] += aa[i]*bb[j];
    }

    float alpha[4];
    #pragma unroll
    for (int i=0;i<4;i++) {
      float mx = fmaxf(fmaxf(Sf[i][0],Sf[i][1]), fmaxf(Sf[i][2],Sf[i][3]));
      #pragma unroll
      for (int off=1; off<16; off<<=1)
        mx = fmaxf(mx, __shfl_xor_sync(0xffffffffu, mx, off));
      float mnew = fmaxf(m_r[i], mx);
      alpha[i] = expf(m_r[i] - mnew);
      float ps = 0.f;
      #pragma unroll
      for (int j=0;j<4;j++) {
        float p = expf(Sf[i][j] - mnew);
        Ps[(tx*4+j)*68 + (ty*4+i)] = p;
        ps += p;
      }
      #pragma unroll
      for (int off=1; off<16; off<<=1)
        ps += __shfl_xor_sync(0xffffffffu, ps, off);
      l_r[i] = l_r[i]*alpha[i] + ps;
      m_r[i] = mnew;
    }
    #pragma unroll
    for (int i=0;i<4;i++)
      #pragma unroll
      for (int j=0;j<4;j++) O[i][j] *= alpha[i];
    __syncthreads();   // Ps visible

    #pragma unroll 4
    for (int kj=0; kj<64; kj++) {
      float4 a4 = *(const float4*)(Ps + kj*68 + ty*4);
      float4 b4 = *(const float4*)(Vs + kj*68 + tx*4);
      float aa[4]={a4.x,a4.y,a4.z,a4.w};
      float bb[4]={b4.x,b4.y,b4.z,b4.w};
      #pragma unroll
      for (int i=0;i<4;i++)
        #pragma unroll
        for (int j=0;j<4;j++) O[i][j] += aa[i]*bb[j];
    }
  }

  #pragma unroll
  for (int i=0;i<4;i++) {
    float inv = 1.0f / l_r[i];
    int q = qt*64 + ty*4 + i;
    float4 v = make_float4(O[i][0]*inv, O[i][1]*inv, O[i][2]*inv, O[i][3]*inv);
    *(float4*)(out + (size_t)(b*TSEQ + q)*DIM + h*HD + tx*4) = v;
  }
}

// ---------------- Router: one warp per token ----------------
__global__ void zero_counts(int* c){ if (threadIdx.x < NE) c[threadIdx.x]=0; }

__global__ void router_kernel(const float* __restrict__ xln2, const float* __restrict__ Wr,
                              int* __restrict__ bucket, float* __restrict__ pairw,
                              int* __restrict__ count) {
  int gw = (int)((blockIdx.x * blockDim.x + threadIdx.x) >> 5);
  int lane = threadIdx.x & 31;
  if (gw >= NTOK) return;
  const float* x = xln2 + (size_t)gw * DIM;
  float lg[NE];
  #pragma unroll
  for (int e=0;e<NE;e++) lg[e]=0.f;
  for (int d=lane; d<DIM; d+=32) {
    float xv = x[d];
    #pragma unroll
    for (int e=0;e<NE;e++) lg[e] += xv * Wr[d*NE + e];
  }
  #pragma unroll
  for (int e=0;e<NE;e++)
    for (int off=16; off; off>>=1) lg[e] += __shfl_xor_sync(0xffffffffu, lg[e], off);
  if (lane == 0) {
    int i0 = 0;
    #pragma unroll
    for (int e=1;e<NE;e++) if (lg[e] > lg[i0]) i0 = e;
    int i1 = (i0==0) ? 1 : 0;
    #pragma unroll
    for (int e=0;e<NE;e++) { if (e==i0) continue; if (lg[e] > lg[i1]) i1 = e; }
    float w0 = 1.f / (1.f + expf(lg[i1] - lg[i0]));
    float w1 = 1.f - w0;
    int p0 = gw*2, p1 = gw*2+1;
    pairw[p0] = w0; pairw[p1] = w1;
    int q0 = atomicAdd(&count[i0], 1); bucket[i0*NPAIR + q0] = p0;
    int q1 = atomicAdd(&count[i1], 1); bucket[i1*NPAIR + q1] = p1;
  }
}

// ---------------- Combine: out = x1 + slot(2t) + slot(2t+1) ----------------
__global__ void combine_kernel(const float* __restrict__ x1, const float* __restrict__ slot,
                               float* __restrict__ out) {
  int idx = blockIdx.x * 256 + threadIdx.x;
  if (idx >= NTOK*DIM) return;
  int t = idx / DIM, j = idx - t*DIM;
  out[idx] = x1[idx] + slot[(size_t)(2*t)*DIM + j] + slot[(size_t)(2*t+1)*DIM + j];
}

extern "C" void kernel_launch(void* const* d_in, const int* in_sizes, int n_in,
                              void* d_out, int out_size) {
  const float* x       = (const float*)d_in[0];
  const float* Wqkv    = (const float*)d_in[1];
  const float* Wproj   = (const float*)d_in[2];
  const float* Wrouter = (const float*)d_in[3];
  const float* W1      = (const float*)d_in[4];
  const float* W2      = (const float*)d_in[5];
  const float* ln1g    = (const float*)d_in[6];
  const float* ln1b    = (const float*)d_in[7];
  const float* ln2g    = (const float*)d_in[8];
  const float* ln2b    = (const float*)d_in[9];
  float* out = (float*)d_out;

  Scratch* s = nullptr;
  cudaGetSymbolAddress((void**)&s, g_s);

  const int ATTN_SMEM = 4*64*68*4;
  cudaFuncSetAttribute(attn_kernel, cudaFuncAttributeMaxDynamicSharedMemorySize, ATTN_SMEM);

  // x -> ln1 -> qkv -> attention -> proj+residual -> x1
  ln_kernel<<<NTOK, 256>>>(x, ln1g, ln1b, s->xln1);
  gemm_kernel<0><<<dim3(QKVN/BN, NTOK/BM, 1), 256>>>(s->xln1, Wqkv, s->qkv,
      NTOK, QKVN, DIM, nullptr, nullptr, nullptr, nullptr);
  attn_kernel<<<dim3(TSEQ/64, NH, NB), 256, ATTN_SMEM>>>(s->qkv, s->attn);
  gemm_kernel<1><<<dim3(DIM/BN, NTOK/BM, 1), 256>>>(s->attn, Wproj, s->x1,
      NTOK, DIM, DIM, nullptr, nullptr, x, nullptr);

  // x1 -> ln2 -> router -> MoE (gathered expert GEMMs) -> combine
  ln_kernel<<<NTOK, 256>>>(s->x1, ln2g, ln2b, s->xln2);
  zero_counts<<<1, 32>>>(s->count);
  router_kernel<<<NTOK/8, 256>>>(s->xln2, Wrouter, s->bucket, s->pairw, s->count);
  gemm_kernel<2><<<dim3(FFD/BN, NPAIR/BM, NE), 256>>>(s->xln2, W1, s->H,
      0, FFD, DIM, s->bucket, s->count, nullptr, nullptr);
  gemm_kernel<3><<<dim3(DIM/BN, NPAIR/BM, NE), 256>>>(s->H, W2, s->slot,
      0, DIM, FFD, s->bucket, s->count, nullptr, s->pairw);
  combine_kernel<<<(NTOK*DIM)/256, 256>>>(s->x1, s->slot, out);
}

// round 2
// speedup vs baseline: 2.0107x; 2.0107x over previous
#include <cuda_runtime.h>
#include <math.h>
#include <stdint.h>

#define NTOK 4096
#define DIM 768
#define QKVN (3*DIM)
#define FFD 3072
#define NE 8
#define NPAIR (NTOK*2)
#define TSEQ 1024
#define NB 4
#define NH 12
#define HD 64

struct Scratch {
  float xln1[(size_t)NTOK*DIM];
  float qkv[(size_t)NTOK*QKVN];
  float attn[(size_t)NTOK*DIM];
  float x1[(size_t)NTOK*DIM];
  float xln2[(size_t)NTOK*DIM];
  float H[(size_t)NPAIR*FFD];
  float slot[(size_t)NPAIR*DIM];
  float pairw[NPAIR];
  int bucket[NE*NPAIR];
  int count[NE];
};
__device__ Scratch g_s;

__device__ __forceinline__ float gelu_f(float v) {
  return 0.5f * v * (1.0f + erff(v * 0.70710678118654752f));
}

__device__ __forceinline__ float to_tf32(float x) {
  unsigned r;
  asm("cvt.rna.tf32.f32 %0, %1;" : "=r"(r) : "f"(x));
  return __uint_as_float(r);
}

__device__ __forceinline__ void mma_tf32(float* c, const float* a, const float* b) {
  asm volatile(
    "mma.sync.aligned.m16n8k8.row.col.f32.tf32.tf32.f32 "
    "{%0,%1,%2,%3},{%4,%5,%6,%7},{%8,%9},{%0,%1,%2,%3};\n"
    : "+f"(c[0]), "+f"(c[1]), "+f"(c[2]), "+f"(c[3])
    : "r"(__float_as_uint(a[0])), "r"(__float_as_uint(a[1])),
      "r"(__float_as_uint(a[2])), "r"(__float_as_uint(a[3])),
      "r"(__float_as_uint(b[0])), "r"(__float_as_uint(b[1])));
}

// ======================= Tensor-core tf32 GEMM ==========================
// MODE 0: C = A@B                         (QKV)       SPLIT=1 (3xTF32)
// MODE 1: C = A@B + resid                 (proj)      SPLIT=1 (3xTF32)
// MODE 2: gather A rows = pair>>1, gelu   (MoE up)    SPLIT=0
// MODE 3: gather A rows = pair, *pairw    (MoE down)  SPLIT=0
// Block tile 128x128, 8 warps as 4(m) x 2(n): warp tile 32x64.
template<int MODE, int SPLIT>
__global__ __launch_bounds__(256)
void mma_gemm(const float* __restrict__ A, const float* __restrict__ Bw,
              float* __restrict__ C, int M, int N, int K,
              const int* __restrict__ bucket, const int* __restrict__ counts,
              const float* __restrict__ resid, const float* __restrict__ pairw)
{
  constexpr int TBK = SPLIT ? 16 : 32;
  constexpr int AST = TBK + 4;           // 20 or 36 floats: frag reads conflict-free
  constexpr int BST = 128 + 8;           // 136 ( == 8 mod 32 ): conflict-free
  constexpr int ASZ = 128 * AST;
  constexpr int BSZ = TBK * BST;
  constexpr int NKS = TBK / 8;
  constexpr int NCH = TBK / 8;           // float4 chunks per thread for A and for B

  extern __shared__ float smx[];
  float* Ah = smx;                                   // [2][ASZ]
  float* Al = SPLIT ? smx + 2*ASZ : (float*)0;       // [2][ASZ]
  float* Bh = smx + (SPLIT ? 4 : 2)*ASZ;             // [2][BSZ]
  float* Bl = SPLIT ? Bh + 2*BSZ : (float*)0;        // [2][BSZ]
  __shared__ int sPair[128];

  int mcount = M;
  const float* B = Bw;
  if constexpr (MODE >= 2) {
    int e = blockIdx.z;
    mcount = counts[e];
    B += (size_t)e * K * N;
  }
  int m0 = blockIdx.y * 128;
  if (m0 >= mcount) return;
  int n0 = blockIdx.x * 128;
  int tid = threadIdx.x;

  if constexpr (MODE >= 2) {
    if (tid < 128) {
      int gm = m0 + tid;
      int gmc = gm < mcount ? gm : mcount - 1;
      sPair[tid] = bucket[blockIdx.z * NPAIR + gmc];
    }
    __syncthreads();
  }

  float4 ra[NCH], rb[NCH];

  auto arowOf = [&](int r) -> int {
    if constexpr (MODE == 2) return sPair[r] >> 1;
    else if constexpr (MODE == 3) return sPair[r];
    else return m0 + r;
  };

  auto ldg = [&](int k0) {
    #pragma unroll
    for (int i = 0; i < NCH; i++) {
      int idx = tid + i*256;
      int row, kc;
      if constexpr (TBK == 32) { row = idx >> 3; kc = idx & 7; }
      else                     { row = idx >> 2; kc = idx & 3; }
      int ar = arowOf(row);
      ra[i] = *(const float4*)(A + (size_t)ar * K + k0 + kc*4);
    }
    #pragma unroll
    for (int i = 0; i < NCH; i++) {
      int idx = tid + i*256;
      int kr = idx >> 5, nc = idx & 31;
      rb[i] = *(const float4*)(B + (size_t)(k0 + kr) * N + n0 + nc*4);
    }
  };

  auto sts = [&](int buf) {
    #pragma unroll
    for (int i = 0; i < NCH; i++) {
      int idx = tid + i*256;
      int row, kc;
      if constexpr (TBK == 32) { row = idx >> 3; kc = idx & 7; }
      else                     { row = idx >> 2; kc = idx & 3; }
      float4 g = ra[i];
      float4 h = make_float4(to_tf32(g.x), to_tf32(g.y), to_tf32(g.z), to_tf32(g.w));
      *(float4*)(Ah + buf*ASZ + row*AST + kc*4) = h;
      if constexpr (SPLIT) {
        float4 l = make_float4(to_tf32(g.x - h.x), to_tf32(g.y - h.y),
                               to_tf32(g.z - h.z), to_tf32(g.w - h.w));
        *(float4*)(Al + buf*ASZ + row*AST + kc*4) = l;
      }
    }
    #pragma unroll
    for (int i = 0; i < NCH; i++) {
      int idx = tid + i*256;
      int kr = idx >> 5, nc = idx & 31;
      float4 g = rb[i];
      float4 h = make_float4(to_tf32(g.x), to_tf32(g.y), to_tf32(g.z), to_tf32(g.w));
      *(float4*)(Bh + buf*BSZ + kr*BST + nc*4) = h;
      if constexpr (SPLIT) {
        float4 l = make_float4(to_tf32(g.x - h.x), to_tf32(g.y - h.y),
                               to_tf32(g.z - h.z), to_tf32(g.w - h.w));
        *(float4*)(Bl + buf*BSZ + kr*BST + nc*4) = l;
      }
    }
  };

  int lane = tid & 31, wid = tid >> 5;
  int wm = wid >> 1, wn = wid & 1;           // 4 x 2 warp grid
  int mb = wm*32 + (lane >> 2);
  int nb = wn*64 + (lane >> 2);
  int kq = lane & 3;

  float acc[2][8][4];
  #pragma unroll
  for (int i = 0; i < 2; i++)
    #pragma unroll
    for (int j = 0; j < 8; j++)
      #pragma unroll
      for (int q = 0; q < 4; q++) acc[i][j][q] = 0.f;

  auto compute = [&](int buf) {
    const float* Asb = Ah + buf*ASZ;
    const float* Bsb = Bh + buf*BSZ;
    #pragma unroll
    for (int s = 0; s < NKS; s++) {
      int ks = s*8 + kq;
      if constexpr (!SPLIT) {
        float bf[8][2];
        #pragma unroll
        for (int nt = 0; nt < 8; nt++) {
          int bw = ks*BST + nb + nt*8;
          bf[nt][0] = Bsb[bw];
          bf[nt][1] = Bsb[bw + 4*BST];
        }
        #pragma unroll
        for (int mt = 0; mt < 2; mt++) {
          int aw = (mb + mt*16)*AST + ks;
          float af[4] = {Asb[aw], Asb[aw + 8*AST], Asb[aw + 4], Asb[aw + 8*AST + 4]};
          #pragma unroll
          for (int nt = 0; nt < 8; nt++) mma_tf32(acc[mt][nt], af, bf[nt]);
        }
      } else {
        const float* Asl = Al + buf*ASZ;
        const float* Bsl = Bl + buf*BSZ;
        float bh[8][2], bl[8][2];
        #pragma unroll
        for (int nt = 0; nt < 8; nt++) {
          int bw = ks*BST + nb + nt*8;
          bh[nt][0] = Bsb[bw]; bh[nt][1] = Bsb[bw + 4*BST];
          bl[nt][0] = Bsl[bw]; bl[nt][1] = Bsl[bw + 4*BST];
        }
        #pragma unroll
        for (int mt = 0; mt < 2; mt++) {
          int aw = (mb + mt*16)*AST + ks;
          float ah[4] = {Asb[aw], Asb[aw + 8*AST], Asb[aw + 4], Asb[aw + 8*AST + 4]};
          float al[4] = {Asl[aw], Asl[aw + 8*AST], Asl[aw + 4], Asl[aw + 8*AST + 4]};
          #pragma unroll
          for (int nt = 0; nt < 8; nt++) {
            mma_tf32(acc[mt][nt], al, bh[nt]);
            mma_tf32(acc[mt][nt], ah, bl[nt]);
            mma_tf32(acc[mt][nt], ah, bh[nt]);
          }
        }
      }
    }
  };

  int nkt = K / TBK;
  ldg(0);
  sts(0);
  __syncthreads();
  for (int kt = 0; kt < nkt; kt++) {
    int cur = kt & 1;
    if (kt + 1 < nkt) ldg((kt + 1) * TBK);
    compute(cur);
    if (kt + 1 < nkt) sts(cur ^ 1);
    __syncthreads();
  }

  // epilogue
  #pragma unroll
  for (int mt = 0; mt < 2; mt++) {
    #pragma unroll
    for (int half = 0; half < 2; half++) {
      int rl = wm*32 + mt*16 + (lane >> 2) + half*8;
      int gmi = m0 + rl;
      if (gmi < mcount) {
        int crow; float w = 1.f;
        if constexpr (MODE >= 2) {
          int p = sPair[rl];
          crow = p;
          if constexpr (MODE == 3) w = pairw[p];
        } else crow = gmi;
        #pragma unroll
        for (int nt = 0; nt < 8; nt++) {
          int col = n0 + wn*64 + nt*8 + (lane & 3)*2;
          float v0 = acc[mt][nt][half*2 + 0];
          float v1 = acc[mt][nt][half*2 + 1];
          if constexpr (MODE == 1) {
            const float* rp = resid + (size_t)gmi * N + col;
            v0 += rp[0]; v1 += rp[1];
          }
          if constexpr (MODE == 2) { v0 = gelu_f(v0); v1 = gelu_f(v1); }
          if constexpr (MODE == 3) { v0 *= w; v1 *= w; }
          *(float2*)(C + (size_t)crow * N + col) = make_float2(v0, v1);
        }
      }
    }
  }
}

// ---------------- LayerNorm ----------------
__global__ void ln_kernel(const float* __restrict__ in, const float* __restrict__ gam,
                          const float* __restrict__ bet, float* __restrict__ out) {
  __shared__ float red[256];
  int row = blockIdx.x;
  int tid = threadIdx.x;
  const float* x = in + (size_t)row * DIM;
  float v0 = x[tid], v1 = x[tid+256], v2 = x[tid+512];
  red[tid] = v0+v1+v2; __syncthreads();
  for (int o=128;o;o>>=1){ if (tid<o) red[tid]+=red[tid+o]; __syncthreads(); }
  float mean = red[0] * (1.0f/DIM);
  __syncthreads();
  float d0=v0-mean, d1=v1-mean, d2=v2-mean;
  red[tid] = d0*d0+d1*d1+d2*d2; __syncthreads();
  for (int o=128;o;o>>=1){ if (tid<o) red[tid]+=red[tid+o]; __syncthreads(); }
  float r = rsqrtf(red[0]*(1.0f/DIM) + 1e-5f);
  float* o = out + (size_t)row*DIM;
  o[tid]     = d0*r*gam[tid]     + bet[tid];
  o[tid+256] = d1*r*gam[tid+256] + bet[tid+256];
  o[tid+512] = d2*r*gam[tid+512] + bet[tid+512];
}

// ---------------- Flash attention (fp32) ----------------
__global__ __launch_bounds__(256)
void attn_kernel(const float* __restrict__ qkv, float* __restrict__ out) {
  extern __shared__ float sm[];
  float* Qs = sm;
  float* Ks = sm + 64*68;
  float* Vs = sm + 2*64*68;
  float* Ps = sm + 3*64*68;
  int qt = blockIdx.x, h = blockIdx.y, b = blockIdx.z;
  int tid = threadIdx.x, tx = tid & 15, ty = tid >> 4;
  const float* base = qkv + (size_t)b * TSEQ * QKVN;
  int qcol = h*HD, kcol = DIM + h*HD, vcol = 2*DIM + h*HD;

  for (int idx = tid; idx < 64*64; idx += 256) {
    int r = idx >> 6, d = idx & 63;
    Qs[d*68 + r] = base[(size_t)(qt*64 + r)*QKVN + qcol + d] * 0.125f;
  }
  float m_r[4], l_r[4], O[4][4];
  #pragma unroll
  for (int i=0;i<4;i++){ m_r[i]=-1e30f; l_r[i]=0.f;
    #pragma unroll
    for (int j=0;j<4;j++) O[i][j]=0.f; }

  for (int kt=0; kt<16; kt++) {
    __syncthreads();
    for (int idx = tid; idx < 64*64; idx += 256) {
      int r = idx >> 6, d = idx & 63;
      const float* rp = base + (size_t)(kt*64 + r)*QKVN;
      Ks[d*68 + r] = rp[kcol + d];
      Vs[r*68 + d] = rp[vcol + d];
    }
    __syncthreads();

    float Sf[4][4];
    #pragma unroll
    for (int i=0;i<4;i++)
      #pragma unroll
      for (int j=0;j<4;j++) Sf[i][j]=0.f;
    #pragma unroll 4
    for (int d=0; d<64; d++) {
      float4 a4 = *(const float4*)(Qs + d*68 + ty*4);
      float4 b4 = *(const float4*)(Ks + d*68 + tx*4);
      float aa[4]={a4.x,a4.y,a4.z,a4.w};
      float bb[4]={b4.x,b4.y,b4.z,b4.w};
      #pragma unroll
      for (int i=0;i<4;i++)
        #pragma unroll
        for (int j=0;j<4;j++) Sf[i][j] += aa[i]*bb[j];
    }

    float alpha[4];
    #pragma unroll
    for (int i=0;i<4;i++) {
      float mx = fmaxf(fmaxf(Sf[i][0],Sf[i][1]), fmaxf(Sf[i][2],Sf[i][3]));
      #pragma unroll
      for (int off=1; off<16; off<<=1)
        mx = fmaxf(mx, __shfl_xor_sync(0xffffffffu, mx, off));
      float mnew = fmaxf(m_r[i], mx);
      alpha[i] = expf(m_r[i] - mnew);
      float ps = 0.f;
      #pragma unroll
      for (int j=0;j<4;j++) {
        float p = expf(Sf[i][j] - mnew);
        Ps[(tx*4+j)*68 + (ty*4+i)] = p;
        ps += p;
      }
      #pragma unroll
      for (int off=1; off<16; off<<=1)
        ps += __shfl_xor_sync(0xffffffffu, ps, off);
      l_r[i] = l_r[i]*alpha[i] + ps;
      m_r[i] = mnew;
    }
    #pragma unroll
    for (int i=0;i<4;i++)
      #pragma unroll
      for (int j=0;j<4;j++) O[i][j] *= alpha[i];
    __syncthreads();

    #pragma unroll 4
    for (int kj=0; kj<64; kj++) {
      float4 a4 = *(const float4*)(Ps + kj*68 + ty*4);
      float4 b4 = *(const float4*)(Vs + kj*68 + tx*4);
      float aa[4]={a4.x,a4.y,a4.z,a4.w};
      float bb[4]={b4.x,b4.y,b4.z,b4.w};
      #pragma unroll
      for (int i=0;i<4;i++)
        #pragma unroll
        for (int j=0;j<4;j++) O[i][j] += aa[i]*bb[j];
    }
  }

  #pragma unroll
  for (int i=0;i<4;i++) {
    float inv = 1.0f / l_r[i];
    int q = qt*64 + ty*4 + i;
    float4 v = make_float4(O[i][0]*inv, O[i][1]*inv, O[i][2]*inv, O[i][3]*inv);
    *(float4*)(out + (size_t)(b*TSEQ + q)*DIM + h*HD + tx*4) = v;
  }
}

// ---------------- Router ----------------
__global__ void zero_counts(int* c){ if (threadIdx.x < NE) c[threadIdx.x]=0; }

__global__ void router_kernel(const float* __restrict__ xln2, const float* __restrict__ Wr,
                              int* __restrict__ bucket, float* __restrict__ pairw,
                              int* __restrict__ count) {
  int gw = (int)((blockIdx.x * blockDim.x + threadIdx.x) >> 5);
  int lane = threadIdx.x & 31;
  if (gw >= NTOK) return;
  const float* x = xln2 + (size_t)gw * DIM;
  float lg[NE];
  #pragma unroll
  for (int e=0;e<NE;e++) lg[e]=0.f;
  for (int d=lane; d<DIM; d+=32) {
    float xv = x[d];
    #pragma unroll
    for (int e=0;e<NE;e++) lg[e] += xv * Wr[d*NE + e];
  }
  #pragma unroll
  for (int e=0;e<NE;e++)
    for (int off=16; off; off>>=1) lg[e] += __shfl_xor_sync(0xffffffffu, lg[e], off);
  if (lane == 0) {
    int i0 = 0;
    #pragma unroll
    for (int e=1;e<NE;e++) if (lg[e] > lg[i0]) i0 = e;
    int i1 = (i0==0) ? 1 : 0;
    #pragma unroll
    for (int e=0;e<NE;e++) { if (e==i0) continue; if (lg[e] > lg[i1]) i1 = e; }
    float w0 = 1.f / (1.f + expf(lg[i1] - lg[i0]));
    float w1 = 1.f - w0;
    int p0 = gw*2, p1 = gw*2+1;
    pairw[p0] = w0; pairw[p1] = w1;
    int q0 = atomicAdd(&count[i0], 1); bucket[i0*NPAIR + q0] = p0;
    int q1 = atomicAdd(&count[i1], 1); bucket[i1*NPAIR + q1] = p1;
  }
}

// ---------------- Combine ----------------
__global__ void combine_kernel(const float* __restrict__ x1, const float* __restrict__ slot,
                               float* __restrict__ out) {
  int idx = blockIdx.x * 256 + threadIdx.x;
  if (idx >= NTOK*DIM) return;
  int t = idx / DIM, j = idx - t*DIM;
  out[idx] = x1[idx] + slot[(size_t)(2*t)*DIM + j] + slot[(size_t)(2*t+1)*DIM + j];
}

extern "C" void kernel_launch(void* const* d_in, const int* in_sizes, int n_in,
                              void* d_out, int out_size) {
  const float* x       = (const float*)d_in[0];
  const float* Wqkv    = (const float*)d_in[1];
  const float* Wproj   = (const float*)d_in[2];
  const float* Wrouter = (const float*)d_in[3];
  const float* W1      = (const float*)d_in[4];
  const float* W2      = (const float*)d_in[5];
  const float* ln1g    = (const float*)d_in[6];
  const float* ln1b    = (const float*)d_in[7];
  const float* ln2g    = (const float*)d_in[8];
  const float* ln2b    = (const float*)d_in[9];
  float* out = (float*)d_out;

  Scratch* s = nullptr;
  cudaGetSymbolAddress((void**)&s, g_s);

  const int ATTN_SMEM = 4*64*68*4;
  cudaFuncSetAttribute(attn_kernel, cudaFuncAttributeMaxDynamicSharedMemorySize, ATTN_SMEM);

  // dynamic smem sizes
  const int SM_N = (2*(128*36) + 2*(32*136)) * 4;   // 71680  (SPLIT=0, TBK=32)
  const int SM_S = (4*(128*20) + 4*(16*136)) * 4;   // 75776  (SPLIT=1, TBK=16)
  cudaFuncSetAttribute(mma_gemm<0,1>, cudaFuncAttributeMaxDynamicSharedMemorySize, SM_S);
  cudaFuncSetAttribute(mma_gemm<1,1>, cudaFuncAttributeMaxDynamicSharedMemorySize, SM_S);
  cudaFuncSetAttribute(mma_gemm<2,0>, cudaFuncAttributeMaxDynamicSharedMemorySize, SM_N);
  cudaFuncSetAttribute(mma_gemm<3,0>, cudaFuncAttributeMaxDynamicSharedMemorySize, SM_N);

  // x -> ln1 -> qkv -> attention -> proj+residual -> x1
  ln_kernel<<<NTOK, 256>>>(x, ln1g, ln1b, s->xln1);
  mma_gemm<0,1><<<dim3(QKVN/128, NTOK/128, 1), 256, SM_S>>>(
      s->xln1, Wqkv, s->qkv, NTOK, QKVN, DIM, nullptr, nullptr, nullptr, nullptr);
  attn_kernel<<<dim3(TSEQ/64, NH, NB), 256, ATTN_SMEM>>>(s->qkv, s->attn);
  mma_gemm<1,1><<<dim3(DIM/128, NTOK/128, 1), 256, SM_S>>>(
      s->attn, Wproj, s->x1, NTOK, DIM, DIM, nullptr, nullptr, x, nullptr);

  // x1 -> ln2 -> router -> MoE -> combine
  ln_kernel<<<NTOK, 256>>>(s->x1, ln2g, ln2b, s->xln2);
  zero_counts<<<1, 32>>>(s->count);
  router_kernel<<<NTOK/8, 256>>>(s->xln2, Wrouter, s->bucket, s->pairw, s->count);
  mma_gemm<2,0><<<dim3(FFD/128, NPAIR/128, NE), 256, SM_N>>>(
      s->xln2, W1, s->H, 0, FFD, DIM, s->bucket, s->count, nullptr, nullptr);
  mma_gemm<3,0><<<dim3(DIM/128, NPAIR/128, NE), 256, SM_N>>>(
      s->H, W2, s->slot, 0, DIM, FFD, s->bucket, s->count, nullptr, s->pairw);
  combine_kernel<<<(NTOK*DIM)/256, 256>>>(s->x1, s->slot, out);
}

// round 3
// speedup vs baseline: 2.1713x; 1.0798x over previous
#include <cuda_runtime.h>
#include <math.h>
#include <stdint.h>

#define NTOK 4096
#define DIM 768
#define QKVN (3*DIM)
#define FFD 3072
#define NE 8
#define NPAIR (NTOK*2)
#define TSEQ 1024
#define NB 4
#define NH 12
#define HD 64

struct Scratch {
  float xln1[(size_t)NTOK*DIM];
  float qkv[(size_t)NTOK*QKVN];
  float attn[(size_t)NTOK*DIM];
  float x1[(size_t)NTOK*DIM];
  float xln2[(size_t)NTOK*DIM];
  float H[(size_t)NPAIR*FFD];
  float slot[(size_t)NPAIR*DIM];
  float pairw[NPAIR];
  int bucket[NE*NPAIR];
  int count[NE];
};
__device__ Scratch g_s;

__device__ __forceinline__ float gelu_f(float v) {
  return 0.5f * v * (1.0f + erff(v * 0.70710678118654752f));
}

__device__ __forceinline__ float to_tf32(float x) {
  unsigned r;
  asm("cvt.rna.tf32.f32 %0, %1;" : "=r"(r) : "f"(x));
  return __uint_as_float(r);
}

__device__ __forceinline__ void mma_tf32(float* c, const float* a, const float* b) {
  asm volatile(
    "mma.sync.aligned.m16n8k8.row.col.f32.tf32.tf32.f32 "
    "{%0,%1,%2,%3},{%4,%5,%6,%7},{%8,%9},{%0,%1,%2,%3};\n"
    : "+f"(c[0]), "+f"(c[1]), "+f"(c[2]), "+f"(c[3])
    : "r"(__float_as_uint(a[0])), "r"(__float_as_uint(a[1])),
      "r"(__float_as_uint(a[2])), "r"(__float_as_uint(a[3])),
      "r"(__float_as_uint(b[0])), "r"(__float_as_uint(b[1])));
}

__device__ __forceinline__ void cp_async16(float* dst, const float* src) {
  uint32_t d = (uint32_t)__cvta_generic_to_shared(dst);
  asm volatile("cp.async.cg.shared.global [%0], [%1], 16;\n" :: "r"(d), "l"(src));
}
__device__ __forceinline__ void cp_commit() {
  asm volatile("cp.async.commit_group;\n");
}
template<int N>
__device__ __forceinline__ void cp_wait() {
  asm volatile("cp.async.wait_group %0;\n" :: "n"(N));
}

// ======================= Multistage tf32 tensor-core GEMM ==========================
// MODE 0: C = A@B                         (QKV)       SPLIT=1 (3xTF32)
// MODE 1: C = A@B + resid                 (proj)      SPLIT=1 (3xTF32)
// MODE 2: gather A rows = pair>>1, gelu   (MoE up)    SPLIT=0
// MODE 3: gather A rows = pair, *pairw    (MoE down)  SPLIT=0
// Block tile 128x128xBK16, 4-stage cp.async pipeline, raw f32 in smem,
// tf32 conversion (and hi/lo split) done at fragment load.
template<int MODE, int SPLIT>
__global__ __launch_bounds__(256, 2)
void mma_gemm(const float* __restrict__ A, const float* __restrict__ Bw,
              float* __restrict__ C, int M, int N, int K,
              const int* __restrict__ bucket, const int* __restrict__ counts,
              const float* __restrict__ resid, const float* __restrict__ pairw)
{
  constexpr int BK  = 16;
  constexpr int STG = 4;
  constexpr int AST = 20;            // A row stride (pad 4): conflict-free frag reads
  constexpr int BST = 136;           // B row stride (pad 8)
  constexpr int ASZ = 128 * AST;     // floats per A stage
  constexpr int BSZ = BK * BST;      // floats per B stage

  extern __shared__ float smx[];
  float* As = smx;                   // [STG][ASZ]
  float* Bs = smx + STG * ASZ;       // [STG][BSZ]
  __shared__ int sPair[128];

  int mcount = M;
  const float* B = Bw;
  if constexpr (MODE >= 2) {
    int e = blockIdx.z;
    mcount = counts[e];
    B += (size_t)e * K * N;
  }
  int m0 = blockIdx.y * 128;
  if (m0 >= mcount) return;
  int n0 = blockIdx.x * 128;
  int tid = threadIdx.x;

  if constexpr (MODE >= 2) {
    if (tid < 128) {
      int gm = m0 + tid;
      int gmc = gm < mcount ? gm : mcount - 1;
      sPair[tid] = bucket[blockIdx.z * NPAIR + gmc];
    }
    __syncthreads();
  }

  // Per-thread gmem source pointers (constant across k-tiles except k offset)
  const float* aSrc[2];
  const float* bSrc[2];
  #pragma unroll
  for (int i = 0; i < 2; i++) {
    int idx = tid + i*256;
    int row = idx >> 2, kc = idx & 3;
    int ar;
    if constexpr (MODE == 2) ar = sPair[row] >> 1;
    else if constexpr (MODE == 3) ar = sPair[row];
    else ar = m0 + row;
    aSrc[i] = A + (size_t)ar * K + kc*4;
    int kr = idx >> 5, nc = idx & 31;
    bSrc[i] = B + (size_t)kr * N + n0 + nc*4;
  }

  auto ldgsts = [&](int stage, int k0) {
    #pragma unroll
    for (int i = 0; i < 2; i++) {
      int idx = tid + i*256;
      int row = idx >> 2, kc = idx & 3;
      cp_async16(As + stage*ASZ + row*AST + kc*4, aSrc[i] + k0);
    }
    #pragma unroll
    for (int i = 0; i < 2; i++) {
      int idx = tid + i*256;
      int kr = idx >> 5, nc = idx & 31;
      cp_async16(Bs + stage*BSZ + kr*BST + nc*4, bSrc[i] + (size_t)k0 * N);
    }
  };

  int lane = tid & 31, wid = tid >> 5;
  int wm = wid >> 1, wn = wid & 1;           // 4(m) x 2(n) warp grid; warp tile 32x64
  int mb = wm*32 + (lane >> 2);
  int nb = wn*64 + (lane >> 2);
  int kq = lane & 3;

  float acc[2][8][4];
  #pragma unroll
  for (int i = 0; i < 2; i++)
    #pragma unroll
    for (int j = 0; j < 8; j++)
      #pragma unroll
      for (int q = 0; q < 4; q++) acc[i][j][q] = 0.f;

  auto compute = [&](int stage) {
    const float* Asb = As + stage*ASZ;
    const float* Bsb = Bs + stage*BSZ;
    #pragma unroll
    for (int s = 0; s < BK/8; s++) {
      int ks = s*8 + kq;
      float ah[2][4], al[2][4];
      #pragma unroll
      for (int mt = 0; mt < 2; mt++) {
        int aw = (mb + mt*16)*AST + ks;
        float r0 = Asb[aw], r1 = Asb[aw + 8*AST], r2 = Asb[aw + 4], r3 = Asb[aw + 8*AST + 4];
        ah[mt][0] = to_tf32(r0); ah[mt][1] = to_tf32(r1);
        ah[mt][2] = to_tf32(r2); ah[mt][3] = to_tf32(r3);
        if constexpr (SPLIT) {
          al[mt][0] = to_tf32(r0 - ah[mt][0]); al[mt][1] = to_tf32(r1 - ah[mt][1]);
          al[mt][2] = to_tf32(r2 - ah[mt][2]); al[mt][3] = to_tf32(r3 - ah[mt][3]);
        }
      }
      #pragma unroll
      for (int nt = 0; nt < 8; nt++) {
        int bw = ks*BST + nb + nt*8;
        float q0 = Bsb[bw], q1 = Bsb[bw + 4*BST];
        float bh[2] = {to_tf32(q0), to_tf32(q1)};
        if constexpr (SPLIT) {
          float bl[2] = {to_tf32(q0 - bh[0]), to_tf32(q1 - bh[1])};
          #pragma unroll
          for (int mt = 0; mt < 2; mt++) {
            mma_tf32(acc[mt][nt], al[mt], bh);
            mma_tf32(acc[mt][nt], ah[mt], bl);
            mma_tf32(acc[mt][nt], ah[mt], bh);
          }
        } else {
          #pragma unroll
          for (int mt = 0; mt < 2; mt++) mma_tf32(acc[mt][nt], ah[mt], bh);
        }
      }
    }
  };

  int nkt = K / BK;
  #pragma unroll
  for (int s = 0; s < STG-1; s++) {
    if (s < nkt) ldgsts(s, s*BK);
    cp_commit();
  }
  for (int kt = 0; kt < nkt; kt++) {
    cp_wait<STG-2>();
    __syncthreads();
    int nxt = kt + STG - 1;
    if (nxt < nkt) ldgsts(nxt % STG, nxt * BK);
    cp_commit();
    compute(kt % STG);
  }

  // epilogue
  #pragma unroll
  for (int mt = 0; mt < 2; mt++) {
    #pragma unroll
    for (int half = 0; half < 2; half++) {
      int rl = wm*32 + mt*16 + (lane >> 2) + half*8;
      int gmi = m0 + rl;
      if (gmi < mcount) {
        int crow; float w = 1.f;
        if constexpr (MODE >= 2) {
          int p = sPair[rl];
          crow = p;
          if constexpr (MODE == 3) w = pairw[p];
        } else crow = gmi;
        #pragma unroll
        for (int nt = 0; nt < 8; nt++) {
          int col = n0 + wn*64 + nt*8 + (lane & 3)*2;
          float v0 = acc[mt][nt][half*2 + 0];
          float v1 = acc[mt][nt][half*2 + 1];
          if constexpr (MODE == 1) {
            const float* rp = resid + (size_t)gmi * N + col;
            v0 += rp[0]; v1 += rp[1];
          }
          if constexpr (MODE == 2) { v0 = gelu_f(v0); v1 = gelu_f(v1); }
          if constexpr (MODE == 3) { v0 *= w; v1 *= w; }
          *(float2*)(C + (size_t)crow * N + col) = make_float2(v0, v1);
        }
      }
    }
  }
}

// ---------------- LayerNorm ----------------
__global__ void ln_kernel(const float* __restrict__ in, const float* __restrict__ gam,
                          const float* __restrict__ bet, float* __restrict__ out) {
  __shared__ float red[256];
  int row = blockIdx.x;
  int tid = threadIdx.x;
  const float* x = in + (size_t)row * DIM;
  float v0 = x[tid], v1 = x[tid+256], v2 = x[tid+512];
  red[tid] = v0+v1+v2; __syncthreads();
  for (int o=128;o;o>>=1){ if (tid<o) red[tid]+=red[tid+o]; __syncthreads(); }
  float mean = red[0] * (1.0f/DIM);
  __syncthreads();
  float d0=v0-mean, d1=v1-mean, d2=v2-mean;
  red[tid] = d0*d0+d1*d1+d2*d2; __syncthreads();
  for (int o=128;o;o>>=1){ if (tid<o) red[tid]+=red[tid+o]; __syncthreads(); }
  float r = rsqrtf(red[0]*(1.0f/DIM) + 1e-5f);
  float* o = out + (size_t)row*DIM;
  o[tid]     = d0*r*gam[tid]     + bet[tid];
  o[tid+256] = d1*r*gam[tid+256] + bet[tid+256];
  o[tid+512] = d2*r*gam[tid+512] + bet[tid+512];
}

// ---------------- Flash attention (fp32) ----------------
__global__ __launch_bounds__(256)
void attn_kernel(const float* __restrict__ qkv, float* __restrict__ out) {
  extern __shared__ float sm[];
  float* Qs = sm;
  float* Ks = sm + 64*68;
  float* Vs = sm + 2*64*68;
  float* Ps = sm + 3*64*68;
  int qt = blockIdx.x, h = blockIdx.y, b = blockIdx.z;
  int tid = threadIdx.x, tx = tid & 15, ty = tid >> 4;
  const float* base = qkv + (size_t)b * TSEQ * QKVN;
  int qcol = h*HD, kcol = DIM + h*HD, vcol = 2*DIM + h*HD;

  for (int idx = tid; idx < 64*64; idx += 256) {
    int r = idx >> 6, d = idx & 63;
    Qs[d*68 + r] = base[(size_t)(qt*64 + r)*QKVN + qcol + d] * 0.125f;
  }
  float m_r[4], l_r[4], O[4][4];
  #pragma unroll
  for (int i=0;i<4;i++){ m_r[i]=-1e30f; l_r[i]=0.f;
    #pragma unroll
    for (int j=0;j<4;j++) O[i][j]=0.f; }

  for (int kt=0; kt<16; kt++) {
    __syncthreads();
    for (int idx = tid; idx < 64*64; idx += 256) {
      int r = idx >> 6, d = idx & 63;
      const float* rp = base + (size_t)(kt*64 + r)*QKVN;
      Ks[d*68 + r] = rp[kcol + d];
      Vs[r*68 + d] = rp[vcol + d];
    }
    __syncthreads();

    float Sf[4][4];
    #pragma unroll
    for (int i=0;i<4;i++)
      #pragma unroll
      for (int j=0;j<4;j++) Sf[i][j]=0.f;
    #pragma unroll 4
    for (int d=0; d<64; d++) {
      float4 a4 = *(const float4*)(Qs + d*68 + ty*4);
      float4 b4 = *(const float4*)(Ks + d*68 + tx*4);
      float aa[4]={a4.x,a4.y,a4.z,a4.w};
      float bb[4]={b4.x,b4.y,b4.z,b4.w};
      #pragma unroll
      for (int i=0;i<4;i++)
        #pragma unroll
        for (int j=0;j<4;j++) Sf[i][j] += aa[i]*bb[j];
    }

    float alpha[4];
    #pragma unroll
    for (int i=0;i<4;i++) {
      float mx = fmaxf(fmaxf(Sf[i][0],Sf[i][1]), fmaxf(Sf[i][2],Sf[i][3]));
      #pragma unroll
      for (int off=1; off<16; off<<=1)
        mx = fmaxf(mx, __shfl_xor_sync(0xffffffffu, mx, off));
      float mnew = fmaxf(m_r[i], mx);
      alpha[i] = expf(m_r[i] - mnew);
      float ps = 0.f;
      #pragma unroll
      for (int j=0;j<4;j++) {
        float p = expf(Sf[i][j] - mnew);
        Ps[(tx*4+j)*68 + (ty*4+i)] = p;
        ps += p;
      }
      #pragma unroll
      for (int off=1; off<16; off<<=1)
        ps += __shfl_xor_sync(0xffffffffu, ps, off);
      l_r[i] = l_r[i]*alpha[i] + ps;
      m_r[i] = mnew;
    }
    #pragma unroll
    for (int i=0;i<4;i++)
      #pragma unroll
      for (int j=0;j<4;j++) O[i][j] *= alpha[i];
    __syncthreads();

    #pragma unroll 4
    for (int kj=0; kj<64; kj++) {
      float4 a4 = *(const float4*)(Ps + kj*68 + ty*4);
      float4 b4 = *(const float4*)(Vs + kj*68 + tx*4);
      float aa[4]={a4.x,a4.y,a4.z,a4.w};
      float bb[4]={b4.x,b4.y,b4.z,b4.w};
      #pragma unroll
      for (int i=0;i<4;i++)
        #pragma unroll
        for (int j=0;j<4;j++) O[i][j] += aa[i]*bb[j];
    }
  }

  #pragma unroll
  for (int i=0;i<4;i++) {
    float inv = 1.0f / l_r[i];
    int q = qt*64 + ty*4 + i;
    float4 v = make_float4(O[i][0]*inv, O[i][1]*inv, O[i][2]*inv, O[i][3]*inv);
    *(float4*)(out + (size_t)(b*TSEQ + q)*DIM + h*HD + tx*4) = v;
  }
}

// ---------------- Router ----------------
__global__ void zero_counts(int* c){ if (threadIdx.x < NE) c[threadIdx.x]=0; }

__global__ void router_kernel(const float* __restrict__ xln2, const float* __restrict__ Wr,
                              int* __restrict__ bucket, float* __restrict__ pairw,
                              int* __restrict__ count) {
  int gw = (int)((blockIdx.x * blockDim.x + threadIdx.x) >> 5);
  int lane = threadIdx.x & 31;
  if (gw >= NTOK) return;
  const float* x = xln2 + (size_t)gw * DIM;
  float lg[NE];
  #pragma unroll
  for (int e=0;e<NE;e++) lg[e]=0.f;
  for (int d=lane; d<DIM; d+=32) {
    float xv = x[d];
    #pragma unroll
    for (int e=0;e<NE;e++) lg[e] += xv * Wr[d*NE + e];
  }
  #pragma unroll
  for (int e=0;e<NE;e++)
    for (int off=16; off; off>>=1) lg[e] += __shfl_xor_sync(0xffffffffu, lg[e], off);
  if (lane == 0) {
    int i0 = 0;
    #pragma unroll
    for (int e=1;e<NE;e++) if (lg[e] > lg[i0]) i0 = e;
    int i1 = (i0==0) ? 1 : 0;
    #pragma unroll
    for (int e=0;e<NE;e++) { if (e==i0) continue; if (lg[e] > lg[i1]) i1 = e; }
    float w0 = 1.f / (1.f + expf(lg[i1] - lg[i0]));
    float w1 = 1.f - w0;
    int p0 = gw*2, p1 = gw*2+1;
    pairw[p0] = w0; pairw[p1] = w1;
    int q0 = atomicAdd(&count[i0], 1); bucket[i0*NPAIR + q0] = p0;
    int q1 = atomicAdd(&count[i1], 1); bucket[i1*NPAIR + q1] = p1;
  }
}

// ---------------- Combine ----------------
__global__ void combine_kernel(const float* __restrict__ x1, const float* __restrict__ slot,
                               float* __restrict__ out) {
  int idx = blockIdx.x * 256 + threadIdx.x;
  if (idx >= NTOK*DIM) return;
  int t = idx / DIM, j = idx - t*DIM;
  out[idx] = x1[idx] + slot[(size_t)(2*t)*DIM + j] + slot[(size_t)(2*t+1)*DIM + j];
}

extern "C" void kernel_launch(void* const* d_in, const int* in_sizes, int n_in,
                              void* d_out, int out_size) {
  const float* x       = (const float*)d_in[0];
  const float* Wqkv    = (const float*)d_in[1];
  const float* Wproj   = (const float*)d_in[2];
  const float* Wrouter = (const float*)d_in[3];
  const float* W1      = (const float*)d_in[4];
  const float* W2      = (const float*)d_in[5];
  const float* ln1g    = (const float*)d_in[6];
  const float* ln1b    = (const float*)d_in[7];
  const float* ln2g    = (const float*)d_in[8];
  const float* ln2b    = (const float*)d_in[9];
  float* out = (float*)d_out;

  Scratch* s = nullptr;
  cudaGetSymbolAddress((void**)&s, g_s);

  const int ATTN_SMEM = 4*64*68*4;
  cudaFuncSetAttribute(attn_kernel, cudaFuncAttributeMaxDynamicSharedMemorySize, ATTN_SMEM);

  // GEMM dynamic smem: 4 stages * (128*20 + 16*136) floats = 75776 bytes
  const int SM_G = (4*(128*20) + 4*(16*136)) * 4;
  cudaFuncSetAttribute(mma_gemm<0,1>, cudaFuncAttributeMaxDynamicSharedMemorySize, SM_G);
  cudaFuncSetAttribute(mma_gemm<1,1>, cudaFuncAttributeMaxDynamicSharedMemorySize, SM_G);
  cudaFuncSetAttribute(mma_gemm<2,0>, cudaFuncAttributeMaxDynamicSharedMemorySize, SM_G);
  cudaFuncSetAttribute(mma_gemm<3,0>, cudaFuncAttributeMaxDynamicSharedMemorySize, SM_G);

  // x -> ln1 -> qkv -> attention -> proj+residual -> x1
  ln_kernel<<<NTOK, 256>>>(x, ln1g, ln1b, s->xln1);
  mma_gemm<0,1><<<dim3(QKVN/128, NTOK/128, 1), 256, SM_G>>>(
      s->xln1, Wqkv, s->qkv, NTOK, QKVN, DIM, nullptr, nullptr, nullptr, nullptr);
  attn_kernel<<<dim3(TSEQ/64, NH, NB), 256, ATTN_SMEM>>>(s->qkv, s->attn);
  mma_gemm<1,1><<<dim3(DIM/128, NTOK/128, 1), 256, SM_G>>>(
      s->attn, Wproj, s->x1, NTOK, DIM, DIM, nullptr, nullptr, x, nullptr);

  // x1 -> ln2 -> router -> MoE -> combine
  ln_kernel<<<NTOK, 256>>>(s->x1, ln2g, ln2b, s->xln2);
  zero_counts<<<1, 32>>>(s->count);
  router_kernel<<<NTOK/8, 256>>>(s->xln2, Wrouter, s->bucket, s->pairw, s->count);
  mma_gemm<2,0><<<dim3(FFD/128, NPAIR/128, NE), 256, SM_G>>>(
      s->xln2, W1, s->H, 0, FFD, DIM, s->bucket, s->count, nullptr, nullptr);
  mma_gemm<3,0><<<dim3(DIM/128, NPAIR/128, NE), 256, SM_G>>>(
      s->H, W2, s->slot, 0, DIM, FFD, s->bucket, s->count, nullptr, s->pairw);
  combine_kernel<<<(NTOK*DIM)/256, 256>>>(s->x1, s->slot, out);
}